// round 6
// baseline (speedup 1.0000x reference)
#include <cuda_runtime.h>
#include <math.h>

#define NROWS 8192
#define NCOLS 8192
#define BC 128                 // columns per block tile
#define BR 128                 // rows per block tile
#define GX (NCOLS / BC)        // 64
#define GY (NROWS / BR)        // 64
#define NBLK (GX * GY)         // 4096
#define NIT (BR / 8)           // 16 row-iterations per block
#define NGRP (NIT / 4)         // 4 groups of 4 (pipelined)

// Scratch state. Invariant: all-zero at kernel_launch entry; the last block
// restores zeros after consuming, so every call sees identical initial state.
__device__ float g_rowsum[NROWS];
__device__ float g_colsum[NCOLS];
__device__ float g_s1part[NBLK];
__device__ unsigned int g_count;

__global__ __launch_bounds__(256) void mi_fused_kernel(const float* __restrict__ ct,
                                                       float* __restrict__ out) {
    const int tx  = threadIdx.x;          // 0..31 : warp lane = 4 columns
    const int ty  = threadIdx.y;          // 0..7  : warp = one row per iteration
    const int lin = ty * 32 + tx;
    const int c0  = blockIdx.x * BC;
    const int r0  = blockIdx.y * BR;

    // lane (tx) covers cols c0+tx*4 .. +3 ; iteration it covers row r0+it*8+ty
    const float4* base =
        reinterpret_cast<const float4*>(ct + (size_t)(r0 + ty) * NCOLS + c0 + tx * 4);
    const int rstride4 = 8 * (NCOLS / 4);          // 8 rows in float4 units

    float ca0 = 0.f, ca1 = 0.f, ca2 = 0.f, ca3 = 0.f;
    float s1a = 0.f, s1b = 0.f, s1c = 0.f, s1d = 0.f;

    // ---- software-pipelined stream: group g+1 loads in flight during group g math ----
    float4 cur[4], nxt[4];
    #pragma unroll
    for (int j = 0; j < 4; ++j)
        cur[j] = __ldcs(base + (size_t)j * rstride4);

    #pragma unroll
    for (int g = 0; g < NGRP; ++g) {
        if (g + 1 < NGRP) {
            #pragma unroll
            for (int j = 0; j < 4; ++j)
                nxt[j] = __ldcs(base + (size_t)((g + 1) * 4 + j) * rstride4);
        }
        #pragma unroll
        for (int j = 0; j < 4; ++j) {
            float x = cur[j].x, y = cur[j].y, z = cur[j].z, w = cur[j].w;
            // inputs >= 0; nonzero values >= 2^-24 so fmaxf(v,1e-30) == v for them,
            // and v==0 contributes 0 * log2(1e-30) = 0.
            s1a = __fmaf_rn(x, __log2f(fmaxf(x, 1e-30f)), s1a);
            s1b = __fmaf_rn(y, __log2f(fmaxf(y, 1e-30f)), s1b);
            s1c = __fmaf_rn(z, __log2f(fmaxf(z, 1e-30f)), s1c);
            s1d = __fmaf_rn(w, __log2f(fmaxf(w, 1e-30f)), s1d);

            ca0 += x; ca1 += y; ca2 += z; ca3 += w;

            // row partial: this warp holds the full 128-col segment of row r
            float rs = (x + y) + (z + w);
            #pragma unroll
            for (int o = 16; o > 0; o >>= 1)
                rs += __shfl_xor_sync(0xffffffffu, rs, o);
            if (tx == 0)
                atomicAdd(&g_rowsum[r0 + (g * 4 + j) * 8 + ty], rs);
        }
        #pragma unroll
        for (int j = 0; j < 4; ++j) cur[j] = nxt[j];
    }

    // ---- column partials: smem transpose-reduce, 1 atomic/col ----
    __shared__ float4 scol4[8][32];
    scol4[ty][tx] = make_float4(ca0, ca1, ca2, ca3);
    __syncthreads();
    if (lin < BC) {
        const float* sc = reinterpret_cast<const float*>(scol4);
        float t = 0.f;
        #pragma unroll
        for (int k = 0; k < 8; ++k) t += sc[k * BC + lin];
        atomicAdd(&g_colsum[c0 + lin], t);
    }

    // ---- S1 block partial -> plain store ----
    {
        float s1 = (s1a + s1b) + (s1c + s1d);
        #pragma unroll
        for (int o = 16; o > 0; o >>= 1)
            s1 += __shfl_xor_sync(0xffffffffu, s1, o);
        __shared__ float sw[8];
        if (tx == 0) sw[ty] = s1;
        __syncthreads();
        if (lin == 0) {
            float t = 0.f;
            #pragma unroll
            for (int k = 0; k < 8; ++k) t += sw[k];
            g_s1part[blockIdx.y * gridDim.x + blockIdx.x] = t;
        }
    }

    // ---- last-block completion (threadfence reduction pattern) ----
    __shared__ unsigned int is_last;
    __threadfence();
    __syncthreads();
    if (lin == 0) {
        unsigned int old = atomicAdd(&g_count, 1u);
        is_last = (old == (unsigned int)(NBLK - 1)) ? 1u : 0u;
    }
    __syncthreads();
    if (!is_last) return;

    __threadfence();  // acquire: see all blocks' writes

    double acc = 0.0;
    for (int i = lin; i < NROWS; i += 256) {
        float s = g_rowsum[i];
        if (s > 0.f) acc -= (double)s * (double)__log2f(s);
        g_rowsum[i] = 0.0f;               // restore invariant
    }
    for (int i = lin; i < NCOLS; i += 256) {
        float s = g_colsum[i];
        if (s > 0.f) acc -= (double)s * (double)__log2f(s);
        g_colsum[i] = 0.0f;               // restore invariant
    }
    for (int i = lin; i < NBLK; i += 256)
        acc += (double)g_s1part[i];       // overwritten each run, no zeroing

    #pragma unroll
    for (int o = 16; o > 0; o >>= 1)
        acc += __shfl_xor_sync(0xffffffffu, acc, o);
    __shared__ double sd[8];
    if (tx == 0) sd[ty] = acc;
    __syncthreads();
    if (lin == 0) {
        double a = 0.0;
        #pragma unroll
        for (int k = 0; k < 8; ++k) a += sd[k];
        out[0] = (float)a;
        g_count = 0u;                     // restore invariant
    }
}

extern "C" void kernel_launch(void* const* d_in, const int* in_sizes, int n_in,
                              void* d_out, int out_size) {
    const float* ct = (const float*)d_in[0];
    float* out = (float*)d_out;

    dim3 grid(GX, GY);
    dim3 block(32, 8);
    mi_fused_kernel<<<grid, block>>>(ct, out);
}

// round 7
// speedup vs baseline: 1.3158x; 1.3158x over previous
#include <cuda_runtime.h>
#include <math.h>

#define NROWS 8192
#define NCOLS 8192
#define W    1024              // cols per block
#define BR   64                // rows per block
#define GX   (NCOLS / W)       // 8
#define GY   (NROWS / BR)      // 128
#define NBLK (GX * GY)         // 1024
#define RB   4                 // rows per batch
#define NB   (BR / RB)         // 16 batches

// Scratch state. Invariant: all-zero at kernel_launch entry; the last block
// restores zeros after consuming, so every call sees identical initial state.
__device__ float g_rowsum[NROWS];
__device__ float g_colsum[NCOLS];
__device__ float g_s1part[NBLK];
__device__ unsigned int g_count;

__global__ __launch_bounds__(256) void mi_fused_kernel(const float* __restrict__ ct,
                                                       float* __restrict__ out) {
    const int tid = threadIdx.x;          // 0..255
    const int w   = tid >> 5;             // warp 0..7
    const int l   = tid & 31;
    const int c0  = blockIdx.x * W;
    const int r0  = blockIdx.y * BR;

    // Thread's fixed column slot: c0 + tid*4 .. +3. Per row step the whole
    // block reads ONE contiguous 4KB segment (256 threads x float4).
    const float4* base =
        reinterpret_cast<const float4*>(ct + (size_t)r0 * NCOLS + c0) + tid;
    const int rstep = NCOLS / 4;          // one row, in float4 units

    __shared__ float sp[RB][256];         // per-thread row partials of a batch

    float ca0 = 0.f, ca1 = 0.f, ca2 = 0.f, ca3 = 0.f;
    float s1a = 0.f, s1b = 0.f, s1c = 0.f, s1d = 0.f;

    float4 cur[RB], nxt[RB];
    #pragma unroll
    for (int j = 0; j < RB; ++j)
        cur[j] = __ldcs(base + (size_t)j * rstep);

    #pragma unroll 1
    for (int b = 0; b < NB; ++b) {
        // prefetch next batch: loads stay in flight through math + reduce
        if (b + 1 < NB) {
            #pragma unroll
            for (int j = 0; j < RB; ++j)
                nxt[j] = __ldcs(base + (size_t)((b + 1) * RB + j) * rstep);
        }

        // lean math, no cross-lane ops
        #pragma unroll
        for (int j = 0; j < RB; ++j) {
            float x = cur[j].x, y = cur[j].y, z = cur[j].z, q = cur[j].w;
            // inputs >= 0; nonzero values >= 2^-24 so fmaxf(v,1e-30) == v,
            // and v==0 contributes 0 * log2(1e-30) = 0.
            s1a = __fmaf_rn(x, __log2f(fmaxf(x, 1e-30f)), s1a);
            s1b = __fmaf_rn(y, __log2f(fmaxf(y, 1e-30f)), s1b);
            s1c = __fmaf_rn(z, __log2f(fmaxf(z, 1e-30f)), s1c);
            s1d = __fmaf_rn(q, __log2f(fmaxf(q, 1e-30f)), s1d);
            ca0 += x; ca1 += y; ca2 += z; ca3 += q;
            sp[j][tid] = (x + y) + (z + q);
        }
        __syncthreads();

        // warps 0..3 each reduce one row of the batch (outside the hot path)
        if (w < RB) {
            float t = 0.f;
            #pragma unroll
            for (int k = 0; k < 8; ++k) t += sp[w][l + k * 32];
            #pragma unroll
            for (int o = 16; o > 0; o >>= 1)
                t += __shfl_xor_sync(0xffffffffu, t, o);
            if (l == 0) atomicAdd(&g_rowsum[r0 + b * RB + w], t);
        }
        __syncthreads();

        #pragma unroll
        for (int j = 0; j < RB; ++j) cur[j] = nxt[j];
    }

    // ---- column sums: thread owns 4 distinct columns -> direct atomics ----
    atomicAdd(&g_colsum[c0 + tid * 4 + 0], ca0);
    atomicAdd(&g_colsum[c0 + tid * 4 + 1], ca1);
    atomicAdd(&g_colsum[c0 + tid * 4 + 2], ca2);
    atomicAdd(&g_colsum[c0 + tid * 4 + 3], ca3);

    // ---- S1 block partial -> plain store ----
    {
        float s1 = (s1a + s1b) + (s1c + s1d);
        #pragma unroll
        for (int o = 16; o > 0; o >>= 1)
            s1 += __shfl_xor_sync(0xffffffffu, s1, o);
        __shared__ float sw[8];
        if (l == 0) sw[w] = s1;
        __syncthreads();
        if (tid == 0) {
            float t = 0.f;
            #pragma unroll
            for (int k = 0; k < 8; ++k) t += sw[k];
            g_s1part[blockIdx.y * gridDim.x + blockIdx.x] = t;
        }
    }

    // ---- last-block completion (threadfence reduction pattern) ----
    __shared__ unsigned int is_last;
    __threadfence();
    __syncthreads();
    if (tid == 0) {
        unsigned int old = atomicAdd(&g_count, 1u);
        is_last = (old == (unsigned int)(NBLK - 1)) ? 1u : 0u;
    }
    __syncthreads();
    if (!is_last) return;

    __threadfence();  // acquire: see all blocks' writes

    double acc = 0.0;
    for (int i = tid; i < NROWS; i += 256) {
        float s = g_rowsum[i];
        if (s > 0.f) acc -= (double)s * (double)__log2f(s);
        g_rowsum[i] = 0.0f;               // restore invariant
    }
    for (int i = tid; i < NCOLS; i += 256) {
        float s = g_colsum[i];
        if (s > 0.f) acc -= (double)s * (double)__log2f(s);
        g_colsum[i] = 0.0f;               // restore invariant
    }
    for (int i = tid; i < NBLK; i += 256)
        acc += (double)g_s1part[i];       // overwritten each run, no zeroing

    #pragma unroll
    for (int o = 16; o > 0; o >>= 1)
        acc += __shfl_xor_sync(0xffffffffu, acc, o);
    __shared__ double sd[8];
    if (l == 0) sd[w] = acc;
    __syncthreads();
    if (tid == 0) {
        double a = 0.0;
        #pragma unroll
        for (int k = 0; k < 8; ++k) a += sd[k];
        out[0] = (float)a;
        g_count = 0u;                     // restore invariant
    }
}

extern "C" void kernel_launch(void* const* d_in, const int* in_sizes, int n_in,
                              void* d_out, int out_size) {
    const float* ct = (const float*)d_in[0];
    float* out = (float*)d_out;

    dim3 grid(GX, GY);
    mi_fused_kernel<<<grid, 256>>>(ct, out);
}